// round 12
// baseline (speedup 1.0000x reference)
#include <cuda_runtime.h>
#include <cuda_bf16.h>
#include <cstdint>

#define BB   64          // batch
#define DD   12          // tree depth
#define VV   128         // vocab/input dim
#define HH   256         // hidden
#define NOPS 20
#define NN   1280        // 5 gates x 256
#define KK   640         // V + 2H
#define RMAX 131072      // BB << (DD-1)
#define KCH  64          // K chunk (bf16 elems) = 128 bytes/row
#define NT   160         // N tile per block: 2 x (5 gates x 16 h)

#define SMEM_BIG   (2 * (128 * 128 + NT * 128))   // 73728  (2-stage, big levels)
#define SMEM_SMALL (5 * (128 * 128 + NT * 128))   // 184320 (5-stage, merged tail)

// ---------------- static device scratch ---------------------------------------
__device__ __nv_bfloat16 g_Wp[NN * KK];                   // packed weights [p][k]
__device__ __nv_bfloat16 g_x[(size_t)BB * 4095 * VV];     // bf16 arg_hot
__device__ __nv_bfloat16 g_h[2][(size_t)RMAX * HH];       // ping-pong h (bf16)
__device__ float         g_c[2][(size_t)RMAX * HH];       // ping-pong c (fp32)
__device__ unsigned      g_bar;                           // global barrier counter

// ---------------- fused x-conversion + weight repack ---------------------------
// blocks [0, 32760): convert arg_hot fp32 -> bf16 (g_x)
// blocks [32760, 35960): repack weights into g_Wp
// packed col p: hb16 = p/80 (h-block of 16), w = p%80, g = w/16, hl = w%16
__global__ void prep_all_kernel(const float* __restrict__ arg_hot,
                                const float* __restrict__ Wiou,
                                const float* __restrict__ Uiou,
                                const float* __restrict__ Wf,
                                const float* __restrict__ Uf)
{
    if (blockIdx.x < 32760) {
        size_t i = ((size_t)blockIdx.x * 256 + threadIdx.x) * 4;
        float4 v = *(const float4*)(arg_hot + i);
        __nv_bfloat162 p0 = __floats2bfloat162_rn(v.x, v.y);
        __nv_bfloat162 p1 = __floats2bfloat162_rn(v.z, v.w);
        uint2 u;
        u.x = *reinterpret_cast<uint32_t*>(&p0);
        u.y = *reinterpret_cast<uint32_t*>(&p1);
        *(uint2*)(g_x + i) = u;
        return;
    }
    int idx = (blockIdx.x - 32760) * 256 + threadIdx.x;
    if (idx == 0) g_bar = 0u;            // reset barrier each launch/replay
    if (idx >= NN * KK) return;
    int p = idx / KK;
    int k = idx % KK;
    int hb16 = p / 80, w = p % 80, g = w / 16, hl = w % 16;
    int hh = hb16 * 16 + hl;
    int n = (g == 0) ? hh : (g == 1) ? 256 + hh : (g == 2) ? 512 + hh
          : (g == 3) ? 768 + hh : 1024 + hh;
    float v;
    if (k < VV) {
        if (n < 768)       v = Wiou[k * 768 + n];
        else if (n < 1024) v = Wf[k * HH + (n - 768)];
        else               v = Wf[k * HH + (n - 1024)];
    } else {
        int j  = (k - VV) >> 8;
        int kh = (k - VV) & 255;
        if (n < 768)       v = Uiou[(j * HH + kh) * 768 + n];
        else if (n < 1024) v = Uf[((0 * 2 + j) * HH + kh) * HH + (n - 768)];
        else               v = Uf[((1 * 2 + j) * HH + kh) * HH + (n - 1024)];
    }
    g_Wp[(size_t)p * KK + k] = __float2bfloat16(v);
}

// ---------------- activations -------------------------------------------------
__device__ __forceinline__ float sigf(float x) {
    return __fdividef(1.0f, 1.0f + __expf(-x));
}
__device__ __forceinline__ float tanh_fast(float x) {
    return __fdividef(2.0f, 1.0f + __expf(-2.0f * x)) - 1.0f;
}

// ---------------- per-level GEMM + gates body ----------------------------------
// Block: 128 rows x 160 cols; 8 warps as 4(M) x 2(N): warp tile 32 x 80.
// STG_T-stage cp.async pipeline (issue-at-end, R8-proven ordering), explicit
// 1-step-ahead fragment double-buffering in the flattened 20-step inner loop.
// GRID ORDER: nt = blockIdx.x (fastest) so the 8 nt-siblings sharing the same
// A tile (x rows + h children) are co-scheduled -> A fetched once from DRAM,
// 7x from L2.
template <int STG_T>
__device__ __forceinline__ void level_body(const float* __restrict__ biou,
                                           const float* __restrict__ bfv,
                                           int level, int leaf, int nch,
                                           char* dsm, float* sb)
{
    const int m = 1 << level;
    const int R = BB * m;
    const __nv_bfloat16* __restrict__ h_prev = g_h[(level + 1) & 1];
    const float*         __restrict__ c_prev = g_c[(level + 1) & 1];
    float*               __restrict__ c_out  = g_c[level & 1];
    __nv_bfloat16*       __restrict__ h_out  = g_h[level & 1];

    const int tid  = threadIdx.x;
    const int lane = tid & 31;
    const int warp = tid >> 5;
    const int wm   = warp & 3;          // 4 warps in M (32 rows each)
    const int wn   = warp >> 2;         // 2 warps in N (80 cols each)
    const int M0   = blockIdx.y * 128;  // M tile (slow grid dim)
    const int nt   = blockIdx.x;        // h-block of 32 (fast grid dim, 0..7)

    for (int i = tid; i < 768; i += 256) sb[i] = biou[i];
    for (int i = tid; i < 256; i += 256) sb[768 + i] = bfv[i];

    const uint32_t smem0 = (uint32_t)__cvta_generic_to_shared(dsm);
    const uint32_t asz = 128 * 128;     // 16 KB A per stage
    const uint32_t ssz = asz + NT * 128;// 36 KB per stage (A then B)

    const int lrow = tid >> 3;   // 0..31
    const int lch  = tid & 7;    // 16B chunk within 128B row

    auto issue = [&](int K0, int buf) {
        const int kg = K0 + lch * 8;
        uint32_t abase = smem0 + buf * ssz;
        #pragma unroll
        for (int it = 0; it < 4; ++it) {
            int row = lrow + it * 32;
            int r   = M0 + row;
            const __nv_bfloat16* src = g_x;   // dummy valid addr for zfill
            int sz = 0;
            if (r < R) {
                int bb   = r >> level;
                int node = r & (m - 1);
                if (kg < VV) {
                    src = g_x + ((size_t)bb * 4095 + (m - 1) + node) * VV + kg;
                    sz  = 16;
                } else if (!leaf) {
                    int j  = (kg - VV) >> 8;
                    int kh = (kg - VV) & 255;
                    src = h_prev + ((size_t)bb * (m << 1) + (node << 1) + j) * HH + kh;
                    sz  = 16;
                }
            }
            uint32_t dst = abase + row * 128 + ((lch ^ (row & 7)) << 4);
            asm volatile("cp.async.cg.shared.global [%0], [%1], 16, %2;\n"
                         :: "r"(dst), "l"(src), "r"(sz));
        }
        uint32_t bbase = abase + asz;
        #pragma unroll
        for (int it = 0; it < 5; ++it) {
            int nrow = lrow + it * 32;
            const __nv_bfloat16* src = g_Wp + (size_t)(nt * NT + nrow) * KK + kg;
            uint32_t dst = bbase + nrow * 128 + ((lch ^ (nrow & 7)) << 4);
            asm volatile("cp.async.cg.shared.global [%0], [%1], 16, 16;\n"
                         :: "r"(dst), "l"(src));
        }
        asm volatile("cp.async.commit_group;\n");
    };

    float acc[2][10][4];
    #pragma unroll
    for (int a = 0; a < 2; ++a)
        #pragma unroll
        for (int c = 0; c < 10; ++c)
            #pragma unroll
            for (int d = 0; d < 4; ++d) acc[a][c][d] = 0.f;

    // prologue: fill up to STG_T stages (empty commits keep group count uniform)
    #pragma unroll
    for (int s = 0; s < STG_T; ++s) {
        if (s < nch) issue(s * KCH, s);
        else         asm volatile("cp.async.commit_group;\n");
    }

    // fragment double buffers
    uint32_t af[2][2][4];     // [buf][mi][frag]
    uint32_t bq[2][4];        // [buf][frag]

    for (int kc = 0; kc < nch; ++kc) {
        asm volatile("cp.async.wait_group %0;\n" :: "n"(STG_T - 1));
        __syncthreads();
        const int stg = kc % STG_T;
        const uint32_t abase = smem0 + stg * ssz;
        const uint32_t bbase = abase + asz;

        // preload step 0 fragments (ks=0, p5=0)
        #pragma unroll
        for (int mi = 0; mi < 2; ++mi) {
            int arow = wm * 32 + mi * 16 + ((lane >> 3) & 1) * 8 + (lane & 7);
            int ach  = (lane >> 4);
            uint32_t aaddr = abase + arow * 128 + ((ach ^ (arow & 7)) << 4);
            asm volatile("ldmatrix.sync.aligned.m8n8.x4.shared.b16 {%0,%1,%2,%3}, [%4];\n"
                         : "=r"(af[0][mi][0]), "=r"(af[0][mi][1]),
                           "=r"(af[0][mi][2]), "=r"(af[0][mi][3]) : "r"(aaddr));
        }
        {
            int brow = wn * 80 + ((lane >> 4) & 1) * 8 + (lane & 7);
            int bch  = ((lane >> 3) & 1);
            uint32_t baddr = bbase + brow * 128 + ((bch ^ (brow & 7)) << 4);
            asm volatile("ldmatrix.sync.aligned.m8n8.x4.shared.b16 {%0,%1,%2,%3}, [%4];\n"
                         : "=r"(bq[0][0]), "=r"(bq[0][1]),
                           "=r"(bq[0][2]), "=r"(bq[0][3]) : "r"(baddr));
        }

        #pragma unroll
        for (int step = 0; step < 20; ++step) {
            const int p5 = step % 5;
            const int ab = (step / 5) & 1;
            // prefetch step+1 fragments
            if (step + 1 < 20) {
                const int nks = ((step + 1) / 5) * 16;
                const int np5 = (step + 1) % 5;
                {
                    int brow = wn * 80 + np5 * 16 + ((lane >> 4) & 1) * 8 + (lane & 7);
                    int bch  = (nks >> 3) + ((lane >> 3) & 1);
                    uint32_t baddr = bbase + brow * 128 + ((bch ^ (brow & 7)) << 4);
                    asm volatile("ldmatrix.sync.aligned.m8n8.x4.shared.b16 {%0,%1,%2,%3}, [%4];\n"
                                 : "=r"(bq[(step + 1) & 1][0]), "=r"(bq[(step + 1) & 1][1]),
                                   "=r"(bq[(step + 1) & 1][2]), "=r"(bq[(step + 1) & 1][3])
                                 : "r"(baddr));
                }
                if (np5 == 0) {
                    const int nab = ((step + 1) / 5) & 1;
                    #pragma unroll
                    for (int mi = 0; mi < 2; ++mi) {
                        int arow = wm * 32 + mi * 16 + ((lane >> 3) & 1) * 8 + (lane & 7);
                        int ach  = (nks >> 3) + (lane >> 4);
                        uint32_t aaddr = abase + arow * 128 + ((ach ^ (arow & 7)) << 4);
                        asm volatile("ldmatrix.sync.aligned.m8n8.x4.shared.b16 {%0,%1,%2,%3}, [%4];\n"
                                     : "=r"(af[nab][mi][0]), "=r"(af[nab][mi][1]),
                                       "=r"(af[nab][mi][2]), "=r"(af[nab][mi][3])
                                     : "r"(aaddr));
                    }
                }
            }
            const uint32_t* b = bq[step & 1];
            #pragma unroll
            for (int mi = 0; mi < 2; ++mi) {
                asm volatile(
                    "mma.sync.aligned.m16n8k16.row.col.f32.bf16.bf16.f32 "
                    "{%0,%1,%2,%3}, {%4,%5,%6,%7}, {%8,%9}, {%0,%1,%2,%3};\n"
                    : "+f"(acc[mi][2 * p5][0]), "+f"(acc[mi][2 * p5][1]),
                      "+f"(acc[mi][2 * p5][2]), "+f"(acc[mi][2 * p5][3])
                    : "r"(af[ab][mi][0]), "r"(af[ab][mi][1]),
                      "r"(af[ab][mi][2]), "r"(af[ab][mi][3]),
                      "r"(b[0]), "r"(b[1]));
                asm volatile(
                    "mma.sync.aligned.m16n8k16.row.col.f32.bf16.bf16.f32 "
                    "{%0,%1,%2,%3}, {%4,%5,%6,%7}, {%8,%9}, {%0,%1,%2,%3};\n"
                    : "+f"(acc[mi][2 * p5 + 1][0]), "+f"(acc[mi][2 * p5 + 1][1]),
                      "+f"(acc[mi][2 * p5 + 1][2]), "+f"(acc[mi][2 * p5 + 1][3])
                    : "r"(af[ab][mi][0]), "r"(af[ab][mi][1]),
                      "r"(af[ab][mi][2]), "r"(af[ab][mi][3]),
                      "r"(b[2]), "r"(b[3]));
            }
        }
        __syncthreads();
        if (kc + STG_T < nch) issue((kc + STG_T) * KCH, stg);
        else                  asm volatile("cp.async.commit_group;\n");
    }

    // ---- fused gate epilogue ----
    // thread owns rows r0+16*mi+8*e, h pairs at hbase + 8*u (+0,+1);
    // gate g lives in acc[mi][2g+u][2e+pair]
    const int r0    = M0 + wm * 32 + (lane >> 2);
    const int hbase = nt * 32 + wn * 16 + ((lane & 3) << 1);
    #pragma unroll
    for (int mi = 0; mi < 2; ++mi) {
        #pragma unroll
        for (int e = 0; e < 2; ++e) {
            int r = r0 + mi * 16 + e * 8;
            if (r >= R) continue;
            float cp0[2][2], cp1[2][2];     // [u][pair]
            if (!leaf) {
                int bb = r >> level, node = r & (m - 1);
                size_t chb = ((size_t)bb * (m << 1) + (node << 1)) * HH;
                #pragma unroll
                for (int u = 0; u < 2; ++u) {
                    // __ldcg: L2-coherent (persistent merged kernel has no
                    // per-launch L1D flush; c rows are rewritten across levels)
                    float2 v0 = __ldcg((const float2*)(c_prev + chb + hbase + u * 8));
                    float2 v1 = __ldcg((const float2*)(c_prev + chb + HH + hbase + u * 8));
                    cp0[u][0] = v0.x; cp0[u][1] = v0.y;
                    cp1[u][0] = v1.x; cp1[u][1] = v1.y;
                }
            } else {
                #pragma unroll
                for (int u = 0; u < 2; ++u)
                    cp0[u][0] = cp0[u][1] = cp1[u][0] = cp1[u][1] = 0.f;
            }
            #pragma unroll
            for (int u = 0; u < 2; ++u) {
                int h = hbase + u * 8;
                float cv[2], hv[2];
                #pragma unroll
                for (int q = 0; q < 2; ++q) {
                    float iv = sigf(acc[mi][0 + u][2 * e + q] + sb[h + q]);
                    float ov = sigf(acc[mi][2 + u][2 * e + q] + sb[256 + h + q]);
                    float uv = tanh_fast(acc[mi][4 + u][2 * e + q] + sb[512 + h + q]);
                    float f0 = sigf(acc[mi][6 + u][2 * e + q] + sb[768 + h + q]);
                    float f1 = sigf(acc[mi][8 + u][2 * e + q] + sb[768 + h + q]);
                    float cc = iv * uv + f0 * cp0[u][q] + f1 * cp1[u][q];
                    cv[q] = cc;
                    hv[q] = ov * tanh_fast(cc);
                }
                *(float2*)(c_out + (size_t)r * HH + h) = make_float2(cv[0], cv[1]);
                __nv_bfloat162 hp = __floats2bfloat162_rn(hv[0], hv[1]);
                *(uint32_t*)(h_out + (size_t)r * HH + h) =
                    *reinterpret_cast<uint32_t*>(&hp);
            }
        }
    }
}

// ---------------- kernels ------------------------------------------------------
// Big levels (11..6): 2-stage / 73 KB — R8-proven optimum (2 CTAs/SM keeps L1D).
__global__ __launch_bounds__(256, 2) void fused_kernel(const float* __restrict__ biou,
                                                       const float* __restrict__ bfv,
                                                       int level, int leaf, int nch)
{
    extern __shared__ __align__(16) char dsm[];
    __shared__ float sb[1024];
    level_body<2>(biou, bfv, level, leaf, nch, dsm, sb);
}

// Levels 5..0 in one persistent launch (128 CTAs, always co-resident).
// Only 128 CTAs chip-wide -> occupancy irrelevant -> use deep 5-stage pipeline
// (184 KB smem, 1 CTA/SM) to collapse the 10 serial K-chunk latencies.
__global__ __launch_bounds__(256, 1) void merged_small_kernel(const float* __restrict__ biou,
                                                              const float* __restrict__ bfv)
{
    extern __shared__ __align__(16) char dsm[];
    __shared__ float sb[1024];
    for (int l = 5; l >= 0; --l) {
        level_body<5>(biou, bfv, l, 0, 10, dsm, sb);
        // grid-wide barrier between levels
        __threadfence();
        __syncthreads();
        if (threadIdx.x == 0) {
            atomicAdd(&g_bar, 1u);
            unsigned target = (unsigned)(6 - l) * 128u;
            while (atomicAdd(&g_bar, 0u) < target) { }
        }
        __syncthreads();
    }
}

// ---------------- actor head + softmax ---------------------------------------
__global__ void final_kernel(const float* __restrict__ actor_w,
                             const float* __restrict__ actor_b,
                             const float* __restrict__ vmask,
                             float* __restrict__ out)
{
    int b = blockIdx.x;
    int lane = threadIdx.x;
    const __nv_bfloat16* hr = g_h[0] + (size_t)b * HH;   // level-0 output, row b

    float lg[NOPS];
    #pragma unroll
    for (int o = 0; o < NOPS; ++o) {
        float s = 0.f;
        for (int hh = lane; hh < HH; hh += 32)
            s += __bfloat162float(hr[hh]) * actor_w[o * HH + hh];
        #pragma unroll
        for (int off = 16; off; off >>= 1) s += __shfl_xor_sync(0xffffffffu, s, off);
        float mk = vmask[b * NOPS + o];
        lg[o] = logf(mk) + s * mk + actor_b[o] * mk;
    }
    if (lane == 0) {
        float mx = -1e30f;
        #pragma unroll
        for (int o = 0; o < NOPS; ++o) {
            lg[o] = lg[o] / 3.0f;           // TEMP
            if (lg[o] > mx) mx = lg[o];
        }
        float ev[NOPS], sum = 0.f;
        #pragma unroll
        for (int o = 0; o < NOPS; ++o) { ev[o] = expf(lg[o] - mx); sum += ev[o]; }
        float inv = 1.0f / sum;
        #pragma unroll
        for (int o = 0; o < NOPS; ++o) out[b * NOPS + o] = ev[o] * inv;
    }
}

// ---------------- launch ------------------------------------------------------
extern "C" void kernel_launch(void* const* d_in, const int* in_sizes, int n_in,
                              void* d_out, int out_size)
{
    const float* arg_hot = (const float*)d_in[0];
    const float* Wiou    = (const float*)d_in[1];
    const float* biou    = (const float*)d_in[2];
    const float* Uiou    = (const float*)d_in[3];
    const float* Wf      = (const float*)d_in[4];
    const float* bfv     = (const float*)d_in[5];
    const float* Uf      = (const float*)d_in[6];
    const float* actor_w = (const float*)d_in[7];
    const float* actor_b = (const float*)d_in[8];
    const float* vmask   = (const float*)d_in[9];
    float* out = (float*)d_out;

    cudaFuncSetAttribute(fused_kernel,
                         cudaFuncAttributeMaxDynamicSharedMemorySize, SMEM_BIG);
    cudaFuncSetAttribute(merged_small_kernel,
                         cudaFuncAttributeMaxDynamicSharedMemorySize, SMEM_SMALL);

    // conv_x: 64*4095*128/(256*4) = 32760 blocks ; prep: 819200/256 = 3200 blocks
    prep_all_kernel<<<35960, 256>>>(arg_hot, Wiou, Uiou, Wf, Uf);

    for (int l = DD - 1; l >= 6; --l) {
        int R = BB << l;
        int leaf = (l == DD - 1) ? 1 : 0;
        int nch  = leaf ? 2 : 10;     // leaf: h_child = 0, only x-K contributes
        // nt fastest: 8 nt-siblings co-scheduled -> A tile shared through L2
        dim3 grid(8, (R + 127) / 128);
        fused_kernel<<<grid, 256, SMEM_BIG>>>(biou, bfv, l, leaf, nch);
    }
    merged_small_kernel<<<dim3(8, 16), 256, SMEM_SMALL>>>(biou, bfv);

    final_kernel<<<BB, 32>>>(actor_w, actor_b, vmask, out);
}

// round 13
// speedup vs baseline: 1.0794x; 1.0794x over previous
#include <cuda_runtime.h>
#include <cuda_bf16.h>
#include <cstdint>

#define BB   64          // batch
#define DD   12          // tree depth
#define VV   128         // vocab/input dim
#define HH   256         // hidden
#define NOPS 20
#define NN   1280        // 5 gates x 256
#define KK   640         // V + 2H
#define RMAX 131072      // BB << (DD-1)
#define KCH  64          // K chunk (bf16 elems) = 128 bytes/row
#define NT   160         // N tile per block: 2 x (5 gates x 16 h)

#define SMEM_BIG   (2 * (128 * 128 + NT * 128))   // 73728  (2-stage, big levels)
#define SMEM_SMALL (5 * (128 * 128 + NT * 128))   // 184320 (5-stage, merged tail)

// ---------------- static device scratch ---------------------------------------
__device__ __nv_bfloat16 g_Wp[NN * KK];                   // packed weights [p][k]
__device__ __nv_bfloat16 g_x[(size_t)BB * 4095 * VV];     // bf16 arg_hot
__device__ __nv_bfloat16 g_h[2][(size_t)RMAX * HH];       // ping-pong h (bf16)
__device__ float         g_c[2][(size_t)RMAX * HH];       // ping-pong c (fp32)
__device__ unsigned      g_bar;                           // global barrier counter

// ---------------- fused x-conversion + weight repack ---------------------------
__global__ void prep_all_kernel(const float* __restrict__ arg_hot,
                                const float* __restrict__ Wiou,
                                const float* __restrict__ Uiou,
                                const float* __restrict__ Wf,
                                const float* __restrict__ Uf)
{
    if (blockIdx.x < 32760) {
        size_t i = ((size_t)blockIdx.x * 256 + threadIdx.x) * 4;
        float4 v = *(const float4*)(arg_hot + i);
        __nv_bfloat162 p0 = __floats2bfloat162_rn(v.x, v.y);
        __nv_bfloat162 p1 = __floats2bfloat162_rn(v.z, v.w);
        uint2 u;
        u.x = *reinterpret_cast<uint32_t*>(&p0);
        u.y = *reinterpret_cast<uint32_t*>(&p1);
        *(uint2*)(g_x + i) = u;
        return;
    }
    int idx = (blockIdx.x - 32760) * 256 + threadIdx.x;
    if (idx == 0) g_bar = 0u;            // reset barrier each launch/replay
    if (idx >= NN * KK) return;
    int p = idx / KK;
    int k = idx % KK;
    int hb16 = p / 80, w = p % 80, g = w / 16, hl = w % 16;
    int hh = hb16 * 16 + hl;
    int n = (g == 0) ? hh : (g == 1) ? 256 + hh : (g == 2) ? 512 + hh
          : (g == 3) ? 768 + hh : 1024 + hh;
    float v;
    if (k < VV) {
        if (n < 768)       v = Wiou[k * 768 + n];
        else if (n < 1024) v = Wf[k * HH + (n - 768)];
        else               v = Wf[k * HH + (n - 1024)];
    } else {
        int j  = (k - VV) >> 8;
        int kh = (k - VV) & 255;
        if (n < 768)       v = Uiou[(j * HH + kh) * 768 + n];
        else if (n < 1024) v = Uf[((0 * 2 + j) * HH + kh) * HH + (n - 768)];
        else               v = Uf[((1 * 2 + j) * HH + kh) * HH + (n - 1024)];
    }
    g_Wp[(size_t)p * KK + k] = __float2bfloat16(v);
}

// ---------------- activations -------------------------------------------------
__device__ __forceinline__ float sigf(float x) {
    return __fdividef(1.0f, 1.0f + __expf(-x));
}
__device__ __forceinline__ float tanh_fast(float x) {
    return __fdividef(2.0f, 1.0f + __expf(-2.0f * x)) - 1.0f;
}

// ---------------- per-level GEMM + gates body ----------------------------------
// CTA tile: (64*MI) rows x 160 cols; 8 warps as 4(M) x 2(N):
//   warp tile (16*MI) x 80.  MI=2 for big levels, MI=1 for small tail levels
//   (twice the CTAs -> the per-SMSP serial HMMA chain halves).
// STG_T-stage cp.async pipeline, issue-at-end, explicit 1-step-ahead fragment
// double-buffering in the flattened 20-step inner loop.
template <int STG_T, int MI>
__device__ __forceinline__ void level_body(const float* __restrict__ biou,
                                           const float* __restrict__ bfv,
                                           int level, int leaf, int nch,
                                           char* dsm, float* sb)
{
    const int MR = 64 * MI;             // rows per CTA
    const int m = 1 << level;
    const int R = BB * m;
    const __nv_bfloat16* __restrict__ h_prev = g_h[(level + 1) & 1];
    const float*         __restrict__ c_prev = g_c[(level + 1) & 1];
    float*               __restrict__ c_out  = g_c[level & 1];
    __nv_bfloat16*       __restrict__ h_out  = g_h[level & 1];

    const int tid  = threadIdx.x;
    const int lane = tid & 31;
    const int warp = tid >> 5;
    const int wm   = warp & 3;          // 4 warps in M
    const int wn   = warp >> 2;         // 2 warps in N (80 cols each)
    const int M0   = blockIdx.y * MR;   // M tile (slow grid dim)
    const int nt   = blockIdx.x;        // h-block of 32 (fast grid dim, 0..7)

    for (int i = tid; i < 768; i += 256) sb[i] = biou[i];
    for (int i = tid; i < 256; i += 256) sb[768 + i] = bfv[i];

    const uint32_t smem0 = (uint32_t)__cvta_generic_to_shared(dsm);
    const uint32_t asz = MR * 128;      // A bytes per stage
    const uint32_t ssz = asz + NT * 128;// stage bytes (A then B)

    const int lrow = tid >> 3;   // 0..31
    const int lch  = tid & 7;    // 16B chunk within 128B row

    auto issue = [&](int K0, int buf) {
        const int kg = K0 + lch * 8;
        uint32_t abase = smem0 + buf * ssz;
        #pragma unroll
        for (int it = 0; it < 2 * MI; ++it) {
            int row = lrow + it * 32;
            int r   = M0 + row;
            const __nv_bfloat16* src = g_x;   // dummy valid addr for zfill
            int sz = 0;
            if (r < R) {
                int bb   = r >> level;
                int node = r & (m - 1);
                if (kg < VV) {
                    src = g_x + ((size_t)bb * 4095 + (m - 1) + node) * VV + kg;
                    sz  = 16;
                } else if (!leaf) {
                    int j  = (kg - VV) >> 8;
                    int kh = (kg - VV) & 255;
                    src = h_prev + ((size_t)bb * (m << 1) + (node << 1) + j) * HH + kh;
                    sz  = 16;
                }
            }
            uint32_t dst = abase + row * 128 + ((lch ^ (row & 7)) << 4);
            asm volatile("cp.async.cg.shared.global [%0], [%1], 16, %2;\n"
                         :: "r"(dst), "l"(src), "r"(sz));
        }
        uint32_t bbase = abase + asz;
        #pragma unroll
        for (int it = 0; it < 5; ++it) {
            int nrow = lrow + it * 32;
            const __nv_bfloat16* src = g_Wp + (size_t)(nt * NT + nrow) * KK + kg;
            uint32_t dst = bbase + nrow * 128 + ((lch ^ (nrow & 7)) << 4);
            asm volatile("cp.async.cg.shared.global [%0], [%1], 16, 16;\n"
                         :: "r"(dst), "l"(src));
        }
        asm volatile("cp.async.commit_group;\n");
    };

    float acc[MI][10][4];
    #pragma unroll
    for (int a = 0; a < MI; ++a)
        #pragma unroll
        for (int c = 0; c < 10; ++c)
            #pragma unroll
            for (int d = 0; d < 4; ++d) acc[a][c][d] = 0.f;

    // prologue: fill up to STG_T stages (empty commits keep group count uniform)
    #pragma unroll
    for (int s = 0; s < STG_T; ++s) {
        if (s < nch) issue(s * KCH, s);
        else         asm volatile("cp.async.commit_group;\n");
    }

    // fragment double buffers
    uint32_t af[2][MI][4];    // [buf][mi][frag]
    uint32_t bq[2][4];        // [buf][frag]

    for (int kc = 0; kc < nch; ++kc) {
        asm volatile("cp.async.wait_group %0;\n" :: "n"(STG_T - 1));
        __syncthreads();
        const int stg = kc % STG_T;
        const uint32_t abase = smem0 + stg * ssz;
        const uint32_t bbase = abase + asz;

        // preload step 0 fragments (ks=0, p5=0)
        #pragma unroll
        for (int mi = 0; mi < MI; ++mi) {
            int arow = wm * (16 * MI) + mi * 16 + ((lane >> 3) & 1) * 8 + (lane & 7);
            int ach  = (lane >> 4);
            uint32_t aaddr = abase + arow * 128 + ((ach ^ (arow & 7)) << 4);
            asm volatile("ldmatrix.sync.aligned.m8n8.x4.shared.b16 {%0,%1,%2,%3}, [%4];\n"
                         : "=r"(af[0][mi][0]), "=r"(af[0][mi][1]),
                           "=r"(af[0][mi][2]), "=r"(af[0][mi][3]) : "r"(aaddr));
        }
        {
            int brow = wn * 80 + ((lane >> 4) & 1) * 8 + (lane & 7);
            int bch  = ((lane >> 3) & 1);
            uint32_t baddr = bbase + brow * 128 + ((bch ^ (brow & 7)) << 4);
            asm volatile("ldmatrix.sync.aligned.m8n8.x4.shared.b16 {%0,%1,%2,%3}, [%4];\n"
                         : "=r"(bq[0][0]), "=r"(bq[0][1]),
                           "=r"(bq[0][2]), "=r"(bq[0][3]) : "r"(baddr));
        }

        #pragma unroll
        for (int step = 0; step < 20; ++step) {
            const int p5 = step % 5;
            const int ab = (step / 5) & 1;
            // prefetch step+1 fragments
            if (step + 1 < 20) {
                const int nks = ((step + 1) / 5) * 16;
                const int np5 = (step + 1) % 5;
                {
                    int brow = wn * 80 + np5 * 16 + ((lane >> 4) & 1) * 8 + (lane & 7);
                    int bch  = (nks >> 3) + ((lane >> 3) & 1);
                    uint32_t baddr = bbase + brow * 128 + ((bch ^ (brow & 7)) << 4);
                    asm volatile("ldmatrix.sync.aligned.m8n8.x4.shared.b16 {%0,%1,%2,%3}, [%4];\n"
                                 : "=r"(bq[(step + 1) & 1][0]), "=r"(bq[(step + 1) & 1][1]),
                                   "=r"(bq[(step + 1) & 1][2]), "=r"(bq[(step + 1) & 1][3])
                                 : "r"(baddr));
                }
                if (np5 == 0) {
                    const int nab = ((step + 1) / 5) & 1;
                    #pragma unroll
                    for (int mi = 0; mi < MI; ++mi) {
                        int arow = wm * (16 * MI) + mi * 16 + ((lane >> 3) & 1) * 8 + (lane & 7);
                        int ach  = (nks >> 3) + (lane >> 4);
                        uint32_t aaddr = abase + arow * 128 + ((ach ^ (arow & 7)) << 4);
                        asm volatile("ldmatrix.sync.aligned.m8n8.x4.shared.b16 {%0,%1,%2,%3}, [%4];\n"
                                     : "=r"(af[nab][mi][0]), "=r"(af[nab][mi][1]),
                                       "=r"(af[nab][mi][2]), "=r"(af[nab][mi][3])
                                     : "r"(aaddr));
                    }
                }
            }
            const uint32_t* b = bq[step & 1];
            #pragma unroll
            for (int mi = 0; mi < MI; ++mi) {
                asm volatile(
                    "mma.sync.aligned.m16n8k16.row.col.f32.bf16.bf16.f32 "
                    "{%0,%1,%2,%3}, {%4,%5,%6,%7}, {%8,%9}, {%0,%1,%2,%3};\n"
                    : "+f"(acc[mi][2 * p5][0]), "+f"(acc[mi][2 * p5][1]),
                      "+f"(acc[mi][2 * p5][2]), "+f"(acc[mi][2 * p5][3])
                    : "r"(af[ab][mi][0]), "r"(af[ab][mi][1]),
                      "r"(af[ab][mi][2]), "r"(af[ab][mi][3]),
                      "r"(b[0]), "r"(b[1]));
                asm volatile(
                    "mma.sync.aligned.m16n8k16.row.col.f32.bf16.bf16.f32 "
                    "{%0,%1,%2,%3}, {%4,%5,%6,%7}, {%8,%9}, {%0,%1,%2,%3};\n"
                    : "+f"(acc[mi][2 * p5 + 1][0]), "+f"(acc[mi][2 * p5 + 1][1]),
                      "+f"(acc[mi][2 * p5 + 1][2]), "+f"(acc[mi][2 * p5 + 1][3])
                    : "r"(af[ab][mi][0]), "r"(af[ab][mi][1]),
                      "r"(af[ab][mi][2]), "r"(af[ab][mi][3]),
                      "r"(b[2]), "r"(b[3]));
            }
        }
        __syncthreads();
        if (kc + STG_T < nch) issue((kc + STG_T) * KCH, stg);
        else                  asm volatile("cp.async.commit_group;\n");
    }

    // ---- fused gate epilogue ----
    const int r0    = M0 + wm * (16 * MI) + (lane >> 2);
    const int hbase = nt * 32 + wn * 16 + ((lane & 3) << 1);
    #pragma unroll
    for (int mi = 0; mi < MI; ++mi) {
        #pragma unroll
        for (int e = 0; e < 2; ++e) {
            int r = r0 + mi * 16 + e * 8;
            if (r >= R) continue;
            float cp0[2][2], cp1[2][2];     // [u][pair]
            if (!leaf) {
                int bb = r >> level, node = r & (m - 1);
                size_t chb = ((size_t)bb * (m << 1) + (node << 1)) * HH;
                #pragma unroll
                for (int u = 0; u < 2; ++u) {
                    float2 v0 = __ldcg((const float2*)(c_prev + chb + hbase + u * 8));
                    float2 v1 = __ldcg((const float2*)(c_prev + chb + HH + hbase + u * 8));
                    cp0[u][0] = v0.x; cp0[u][1] = v0.y;
                    cp1[u][0] = v1.x; cp1[u][1] = v1.y;
                }
            } else {
                #pragma unroll
                for (int u = 0; u < 2; ++u)
                    cp0[u][0] = cp0[u][1] = cp1[u][0] = cp1[u][1] = 0.f;
            }
            #pragma unroll
            for (int u = 0; u < 2; ++u) {
                int h = hbase + u * 8;
                float cv[2], hv[2];
                #pragma unroll
                for (int q = 0; q < 2; ++q) {
                    float iv = sigf(acc[mi][0 + u][2 * e + q] + sb[h + q]);
                    float ov = sigf(acc[mi][2 + u][2 * e + q] + sb[256 + h + q]);
                    float uv = tanh_fast(acc[mi][4 + u][2 * e + q] + sb[512 + h + q]);
                    float f0 = sigf(acc[mi][6 + u][2 * e + q] + sb[768 + h + q]);
                    float f1 = sigf(acc[mi][8 + u][2 * e + q] + sb[768 + h + q]);
                    float cc = iv * uv + f0 * cp0[u][q] + f1 * cp1[u][q];
                    cv[q] = cc;
                    hv[q] = ov * tanh_fast(cc);
                }
                *(float2*)(c_out + (size_t)r * HH + h) = make_float2(cv[0], cv[1]);
                __nv_bfloat162 hp = __floats2bfloat162_rn(hv[0], hv[1]);
                *(uint32_t*)(h_out + (size_t)r * HH + h) =
                    *reinterpret_cast<uint32_t*>(&hp);
            }
        }
    }
}

// ---------------- kernels ------------------------------------------------------
// Big levels (11..6): 2-stage / 73 KB / MR=128 — proven optimum.
__global__ __launch_bounds__(256, 2) void fused_kernel(const float* __restrict__ biou,
                                                       const float* __restrict__ bfv,
                                                       int level, int leaf, int nch)
{
    extern __shared__ __align__(16) char dsm[];
    __shared__ float sb[1024];
    level_body<2, 2>(biou, bfv, level, leaf, nch, dsm, sb);
}

// Levels 5..0 in one persistent launch (128 CTAs, always co-resident).
// l=5: MR=128 (16 M-blocks x 8 = 128 active CTAs).
// l<=4: MR=64 — doubles CTA count per row, halving the per-SMSP serial
// HMMA chain (~23us -> ~6.5us per level). Inactive CTAs compute zeros
// (fully guarded) and join the barrier.
// The actor head + softmax is fused at the end (blockIdx.y==0: 8 blocks x
// 8 warps = 64 batches).
__global__ __launch_bounds__(256, 1) void merged_small_kernel(
    const float* __restrict__ biou, const float* __restrict__ bfv,
    const float* __restrict__ actor_w, const float* __restrict__ actor_b,
    const float* __restrict__ vmask, float* __restrict__ out)
{
    extern __shared__ __align__(16) char dsm[];
    __shared__ float sb[1024];
    for (int l = 5; l >= 0; --l) {
        if (l == 5) level_body<5, 2>(biou, bfv, l, 0, 10, dsm, sb);
        else        level_body<5, 1>(biou, bfv, l, 0, 10, dsm, sb);
        // grid-wide barrier between levels
        __threadfence();
        __syncthreads();
        if (threadIdx.x == 0) {
            atomicAdd(&g_bar, 1u);
            unsigned target = (unsigned)(6 - l) * 128u;
            while (atomicAdd(&g_bar, 0u) < target) { }
        }
        __syncthreads();
    }

    // ---- fused actor head + softmax (after l=0 barrier) ----
    if (blockIdx.y != 0) return;
    int warp = threadIdx.x >> 5;
    int lane = threadIdx.x & 31;
    int b = blockIdx.x * 8 + warp;      // 8 blocks x 8 warps = 64 batches
    const unsigned* hr = (const unsigned*)(g_h[0] + (size_t)b * HH);

    // cache h for this batch in registers (coherent L2 reads)
    float hvv[8];                        // 4 uints = 8 bf16 per lane
    unsigned hu[4];
    #pragma unroll
    for (int i = 0; i < 4; ++i) hu[i] = __ldcg(hr + lane + i * 32);
    #pragma unroll
    for (int i = 0; i < 4; ++i) {
        __nv_bfloat162 p = *reinterpret_cast<__nv_bfloat162*>(&hu[i]);
        hvv[i * 2]     = __bfloat162float(p.x);
        hvv[i * 2 + 1] = __bfloat162float(p.y);
    }

    float lg[NOPS];
    #pragma unroll
    for (int o = 0; o < NOPS; ++o) {
        float s = 0.f;
        #pragma unroll
        for (int i = 0; i < 4; ++i) {
            int hh = (lane + i * 32) * 2;
            s += hvv[i * 2]     * actor_w[o * HH + hh];
            s += hvv[i * 2 + 1] * actor_w[o * HH + hh + 1];
        }
        #pragma unroll
        for (int off = 16; off; off >>= 1) s += __shfl_xor_sync(0xffffffffu, s, off);
        float mk = vmask[b * NOPS + o];
        lg[o] = logf(mk) + s * mk + actor_b[o] * mk;
    }
    if (lane == 0) {
        float mx = -1e30f;
        #pragma unroll
        for (int o = 0; o < NOPS; ++o) {
            lg[o] = lg[o] / 3.0f;           // TEMP
            if (lg[o] > mx) mx = lg[o];
        }
        float ev[NOPS], sum = 0.f;
        #pragma unroll
        for (int o = 0; o < NOPS; ++o) { ev[o] = expf(lg[o] - mx); sum += ev[o]; }
        float inv = 1.0f / sum;
        #pragma unroll
        for (int o = 0; o < NOPS; ++o) out[b * NOPS + o] = ev[o] * inv;
    }
}

// ---------------- launch ------------------------------------------------------
extern "C" void kernel_launch(void* const* d_in, const int* in_sizes, int n_in,
                              void* d_out, int out_size)
{
    const float* arg_hot = (const float*)d_in[0];
    const float* Wiou    = (const float*)d_in[1];
    const float* biou    = (const float*)d_in[2];
    const float* Uiou    = (const float*)d_in[3];
    const float* Wf      = (const float*)d_in[4];
    const float* bfv     = (const float*)d_in[5];
    const float* Uf      = (const float*)d_in[6];
    const float* actor_w = (const float*)d_in[7];
    const float* actor_b = (const float*)d_in[8];
    const float* vmask   = (const float*)d_in[9];
    float* out = (float*)d_out;

    cudaFuncSetAttribute(fused_kernel,
                         cudaFuncAttributeMaxDynamicSharedMemorySize, SMEM_BIG);
    cudaFuncSetAttribute(merged_small_kernel,
                         cudaFuncAttributeMaxDynamicSharedMemorySize, SMEM_SMALL);

    // conv_x: 64*4095*128/(256*4) = 32760 blocks ; prep: 819200/256 = 3200 blocks
    prep_all_kernel<<<35960, 256>>>(arg_hot, Wiou, Uiou, Wf, Uf);

    for (int l = DD - 1; l >= 6; --l) {
        int R = BB << l;
        int leaf = (l == DD - 1) ? 1 : 0;
        int nch  = leaf ? 2 : 10;     // leaf: h_child = 0, only x-K contributes
        // nt fastest: 8 nt-siblings co-scheduled -> A tile shared through L2
        dim3 grid(8, (R + 127) / 128);
        fused_kernel<<<grid, 256, SMEM_BIG>>>(biou, bfv, l, leaf, nch);
    }
    merged_small_kernel<<<dim3(8, 16), 256, SMEM_SMALL>>>(
        biou, bfv, actor_w, actor_b, vmask, out);
}

// round 15
// speedup vs baseline: 1.2266x; 1.1363x over previous
#include <cuda_runtime.h>
#include <cuda_bf16.h>
#include <cstdint>

#define BB   64          // batch
#define DD   12          // tree depth
#define VV   128         // vocab/input dim
#define HH   256         // hidden
#define NOPS 20
#define NN   1280        // 5 gates x 256
#define KK   640         // V + 2H
#define RMAX 131072      // BB << (DD-1)
#define KCH  64          // K chunk (bf16 elems) = 128 bytes/row
#define NT   160         // N tile per block: 2 x (5 gates x 16 h)

#define SMEM_BIG   (2 * (128 * 128 + NT * 128))   // 73728  (2-stage, big levels)
#define SMEM_SMALL (5 * (128 * 128 + NT * 128))   // 184320 (5-stage, merged tail)

// ---------------- static device scratch ---------------------------------------
__device__ __nv_bfloat16 g_Wp[NN * KK];                   // packed weights [p][k]
__device__ __nv_bfloat16 g_x[(size_t)BB * 4095 * VV];     // bf16 arg_hot
__device__ __nv_bfloat16 g_h[2][(size_t)RMAX * HH];       // ping-pong h (bf16)
__device__ float         g_c[2][(size_t)RMAX * HH];       // ping-pong c (fp32)
__device__ unsigned      g_bar;                           // global barrier counter

// ---------------- fused x-conversion + weight repack ---------------------------
__global__ void prep_all_kernel(const float* __restrict__ arg_hot,
                                const float* __restrict__ Wiou,
                                const float* __restrict__ Uiou,
                                const float* __restrict__ Wf,
                                const float* __restrict__ Uf)
{
    if (blockIdx.x < 32760) {
        size_t i = ((size_t)blockIdx.x * 256 + threadIdx.x) * 4;
        float4 v = *(const float4*)(arg_hot + i);
        __nv_bfloat162 p0 = __floats2bfloat162_rn(v.x, v.y);
        __nv_bfloat162 p1 = __floats2bfloat162_rn(v.z, v.w);
        uint2 u;
        u.x = *reinterpret_cast<uint32_t*>(&p0);
        u.y = *reinterpret_cast<uint32_t*>(&p1);
        *(uint2*)(g_x + i) = u;
        return;
    }
    int idx = (blockIdx.x - 32760) * 256 + threadIdx.x;
    if (idx == 0) g_bar = 0u;            // reset barrier each launch/replay
    if (idx >= NN * KK) return;
    int p = idx / KK;
    int k = idx % KK;
    int hb16 = p / 80, w = p % 80, g = w / 16, hl = w % 16;
    int hh = hb16 * 16 + hl;
    int n = (g == 0) ? hh : (g == 1) ? 256 + hh : (g == 2) ? 512 + hh
          : (g == 3) ? 768 + hh : 1024 + hh;
    float v;
    if (k < VV) {
        if (n < 768)       v = Wiou[k * 768 + n];
        else if (n < 1024) v = Wf[k * HH + (n - 768)];
        else               v = Wf[k * HH + (n - 1024)];
    } else {
        int j  = (k - VV) >> 8;
        int kh = (k - VV) & 255;
        if (n < 768)       v = Uiou[(j * HH + kh) * 768 + n];
        else if (n < 1024) v = Uf[((0 * 2 + j) * HH + kh) * HH + (n - 768)];
        else               v = Uf[((1 * 2 + j) * HH + kh) * HH + (n - 1024)];
    }
    g_Wp[(size_t)p * KK + k] = __float2bfloat16(v);
}

// ---------------- activations -------------------------------------------------
__device__ __forceinline__ float sigf(float x) {
    return __fdividef(1.0f, 1.0f + __expf(-x));
}
__device__ __forceinline__ float tanh_fast(float x) {
    return __fdividef(2.0f, 1.0f + __expf(-2.0f * x)) - 1.0f;
}

// =============================================================================
// Specialized BIG-LEVEL body (levels 11..6): LEVEL constexpr, exact grids (no
// guards), incremental u32-offset gather (all per-chunk address math reduced
// to `off += 128`, recomputed only at the two phase boundaries c=2 / c=6).
// CTA 128 x 160, 8 warps 4(M) x 2(N), 2-stage pipeline, fragment dbl-buffer.
// =============================================================================
template <int LEVEL>
__device__ __forceinline__ void big_body(const float* __restrict__ biou,
                                         const float* __restrict__ bfv,
                                         char* dsm, float* sb)
{
    constexpr bool LEAF = (LEVEL == DD - 1);
    constexpr int  NCH  = LEAF ? 2 : 10;
    constexpr int  m    = 1 << LEVEL;

    const float* __restrict__ c_prev = g_c[(LEVEL + 1) & 1];
    float*       __restrict__ c_out  = g_c[LEVEL & 1];
    __nv_bfloat16* __restrict__ h_out = g_h[LEVEL & 1];

    const int tid  = threadIdx.x;
    const int lane = tid & 31;
    const int warp = tid >> 5;
    const int wm   = warp & 3;
    const int wn   = warp >> 2;
    const int M0   = blockIdx.y * 128;
    const int nt   = blockIdx.x;

    for (int i = tid; i < 768; i += 256) sb[i] = biou[i];
    for (int i = tid; i < 256; i += 256) sb[768 + i] = bfv[i];

    const uint32_t smem0 = (uint32_t)__cvta_generic_to_shared(dsm);
    const uint32_t asz = 128 * 128;
    const uint32_t ssz = asz + NT * 128;

    const int lrow = tid >> 3;
    const int lch  = tid & 7;
    const uint32_t aswz = (uint32_t)((lch ^ (lrow & 7)) << 4) + lrow * 128;

    // incremental gather state: base pointer + u32 byte offsets per it
    const char* ag = (const char*)g_x;
    uint32_t aoff[4];
    #pragma unroll
    for (int it = 0; it < 4; ++it) {
        int r = M0 + lrow + it * 32;
        int bb = r >> LEVEL, node = r & (m - 1);
        aoff[it] = (uint32_t)((((size_t)bb * 4095 + (m - 1) + node) * VV + lch * 8) * 2);
    }
    uint32_t boff[5];
    #pragma unroll
    for (int it = 0; it < 5; ++it)
        boff[it] = (uint32_t)(((size_t)(nt * NT + lrow + it * 32) * KK + lch * 8) * 2);

    auto issue = [&](int c, int buf) {
        if (!LEAF && (c == 2 || c == 6)) {
            const int j = (c == 6);
            #pragma unroll
            for (int it = 0; it < 4; ++it) {
                int r = M0 + lrow + it * 32;
                int bb = r >> LEVEL, node = r & (m - 1);
                aoff[it] = (uint32_t)((((size_t)bb * (m << 1) + (node << 1) + j) * HH
                                       + lch * 8) * 2);
            }
            ag = (const char*)g_h[(LEVEL + 1) & 1];
        }
        uint32_t abase = smem0 + buf * ssz + aswz;
        #pragma unroll
        for (int it = 0; it < 4; ++it) {
            asm volatile("cp.async.cg.shared.global [%0], [%1], 16;\n"
                         :: "r"(abase + it * 4096), "l"(ag + aoff[it]));
            aoff[it] += 128;
        }
        uint32_t bbase = smem0 + buf * ssz + asz + aswz;
        #pragma unroll
        for (int it = 0; it < 5; ++it) {
            asm volatile("cp.async.cg.shared.global [%0], [%1], 16;\n"
                         :: "r"(bbase + it * 4096), "l"((const char*)g_Wp + boff[it]));
            boff[it] += 128;
        }
        asm volatile("cp.async.commit_group;\n");
    };

    float acc[2][10][4];
    #pragma unroll
    for (int a = 0; a < 2; ++a)
        #pragma unroll
        for (int c = 0; c < 10; ++c)
            #pragma unroll
            for (int d = 0; d < 4; ++d) acc[a][c][d] = 0.f;

    issue(0, 0);
    issue(1, 1);

    uint32_t af[2][2][4];
    uint32_t bq[2][4];

    #pragma unroll 1
    for (int kc = 0; kc < NCH; ++kc) {
        asm volatile("cp.async.wait_group 1;\n");
        __syncthreads();
        const uint32_t abase = smem0 + (kc & 1) * ssz;
        const uint32_t bbase = abase + asz;

        // preload step 0 fragments
        #pragma unroll
        for (int mi = 0; mi < 2; ++mi) {
            int arow = wm * 32 + mi * 16 + ((lane >> 3) & 1) * 8 + (lane & 7);
            int ach  = (lane >> 4);
            uint32_t aaddr = abase + arow * 128 + ((ach ^ (arow & 7)) << 4);
            asm volatile("ldmatrix.sync.aligned.m8n8.x4.shared.b16 {%0,%1,%2,%3}, [%4];\n"
                         : "=r"(af[0][mi][0]), "=r"(af[0][mi][1]),
                           "=r"(af[0][mi][2]), "=r"(af[0][mi][3]) : "r"(aaddr));
        }
        {
            int brow = wn * 80 + ((lane >> 4) & 1) * 8 + (lane & 7);
            int bch  = ((lane >> 3) & 1);
            uint32_t baddr = bbase + brow * 128 + ((bch ^ (brow & 7)) << 4);
            asm volatile("ldmatrix.sync.aligned.m8n8.x4.shared.b16 {%0,%1,%2,%3}, [%4];\n"
                         : "=r"(bq[0][0]), "=r"(bq[0][1]),
                           "=r"(bq[0][2]), "=r"(bq[0][3]) : "r"(baddr));
        }

        #pragma unroll
        for (int step = 0; step < 20; ++step) {
            const int p5 = step % 5;
            const int ab = (step / 5) & 1;
            if (step + 1 < 20) {
                const int nks = ((step + 1) / 5) * 16;
                const int np5 = (step + 1) % 5;
                {
                    int brow = wn * 80 + np5 * 16 + ((lane >> 4) & 1) * 8 + (lane & 7);
                    int bch  = (nks >> 3) + ((lane >> 3) & 1);
                    uint32_t baddr = bbase + brow * 128 + ((bch ^ (brow & 7)) << 4);
                    asm volatile("ldmatrix.sync.aligned.m8n8.x4.shared.b16 {%0,%1,%2,%3}, [%4];\n"
                                 : "=r"(bq[(step + 1) & 1][0]), "=r"(bq[(step + 1) & 1][1]),
                                   "=r"(bq[(step + 1) & 1][2]), "=r"(bq[(step + 1) & 1][3])
                                 : "r"(baddr));
                }
                if (np5 == 0) {
                    const int nab = ((step + 1) / 5) & 1;
                    #pragma unroll
                    for (int mi = 0; mi < 2; ++mi) {
                        int arow = wm * 32 + mi * 16 + ((lane >> 3) & 1) * 8 + (lane & 7);
                        int ach  = (nks >> 3) + (lane >> 4);
                        uint32_t aaddr = abase + arow * 128 + ((ach ^ (arow & 7)) << 4);
                        asm volatile("ldmatrix.sync.aligned.m8n8.x4.shared.b16 {%0,%1,%2,%3}, [%4];\n"
                                     : "=r"(af[nab][mi][0]), "=r"(af[nab][mi][1]),
                                       "=r"(af[nab][mi][2]), "=r"(af[nab][mi][3])
                                     : "r"(aaddr));
                    }
                }
            }
            const uint32_t* b = bq[step & 1];
            #pragma unroll
            for (int mi = 0; mi < 2; ++mi) {
                asm volatile(
                    "mma.sync.aligned.m16n8k16.row.col.f32.bf16.bf16.f32 "
                    "{%0,%1,%2,%3}, {%4,%5,%6,%7}, {%8,%9}, {%0,%1,%2,%3};\n"
                    : "+f"(acc[mi][2 * p5][0]), "+f"(acc[mi][2 * p5][1]),
                      "+f"(acc[mi][2 * p5][2]), "+f"(acc[mi][2 * p5][3])
                    : "r"(af[ab][mi][0]), "r"(af[ab][mi][1]),
                      "r"(af[ab][mi][2]), "r"(af[ab][mi][3]),
                      "r"(b[0]), "r"(b[1]));
                asm volatile(
                    "mma.sync.aligned.m16n8k16.row.col.f32.bf16.bf16.f32 "
                    "{%0,%1,%2,%3}, {%4,%5,%6,%7}, {%8,%9}, {%0,%1,%2,%3};\n"
                    : "+f"(acc[mi][2 * p5 + 1][0]), "+f"(acc[mi][2 * p5 + 1][1]),
                      "+f"(acc[mi][2 * p5 + 1][2]), "+f"(acc[mi][2 * p5 + 1][3])
                    : "r"(af[ab][mi][0]), "r"(af[ab][mi][1]),
                      "r"(af[ab][mi][2]), "r"(af[ab][mi][3]),
                      "r"(b[2]), "r"(b[3]));
            }
        }
        __syncthreads();
        if (kc + 2 < NCH) issue(kc + 2, kc & 1);
        else              asm volatile("cp.async.commit_group;\n");
    }

    // ---- fused gate epilogue (no row guards: big grids are exact) ----
    const int r0    = M0 + wm * 32 + (lane >> 2);
    const int hbase = nt * 32 + wn * 16 + ((lane & 3) << 1);
    #pragma unroll
    for (int mi = 0; mi < 2; ++mi) {
        #pragma unroll
        for (int e = 0; e < 2; ++e) {
            int r = r0 + mi * 16 + e * 8;
            float cp0[2][2], cp1[2][2];
            if (!LEAF) {
                int bb = r >> LEVEL, node = r & (m - 1);
                size_t chb = ((size_t)bb * (m << 1) + (node << 1)) * HH;
                #pragma unroll
                for (int u = 0; u < 2; ++u) {
                    float2 v0 = __ldcg((const float2*)(c_prev + chb + hbase + u * 8));
                    float2 v1 = __ldcg((const float2*)(c_prev + chb + HH + hbase + u * 8));
                    cp0[u][0] = v0.x; cp0[u][1] = v0.y;
                    cp1[u][0] = v1.x; cp1[u][1] = v1.y;
                }
            } else {
                #pragma unroll
                for (int u = 0; u < 2; ++u)
                    cp0[u][0] = cp0[u][1] = cp1[u][0] = cp1[u][1] = 0.f;
            }
            #pragma unroll
            for (int u = 0; u < 2; ++u) {
                int h = hbase + u * 8;
                float cv[2], hv[2];
                #pragma unroll
                for (int q = 0; q < 2; ++q) {
                    float iv = sigf(acc[mi][0 + u][2 * e + q] + sb[h + q]);
                    float ov = sigf(acc[mi][2 + u][2 * e + q] + sb[256 + h + q]);
                    float uv = tanh_fast(acc[mi][4 + u][2 * e + q] + sb[512 + h + q]);
                    float f0 = sigf(acc[mi][6 + u][2 * e + q] + sb[768 + h + q]);
                    float f1 = sigf(acc[mi][8 + u][2 * e + q] + sb[768 + h + q]);
                    float cc = iv * uv + f0 * cp0[u][q] + f1 * cp1[u][q];
                    cv[q] = cc;
                    hv[q] = ov * tanh_fast(cc);
                }
                *(float2*)(c_out + (size_t)r * HH + h) = make_float2(cv[0], cv[1]);
                __nv_bfloat162 hp = __floats2bfloat162_rn(hv[0], hv[1]);
                *(uint32_t*)(h_out + (size_t)r * HH + h) =
                    *reinterpret_cast<uint32_t*>(&hp);
            }
        }
    }
}

template <int LEVEL>
__global__ __launch_bounds__(256, 2) void fused_big(const float* __restrict__ biou,
                                                    const float* __restrict__ bfv)
{
    extern __shared__ __align__(16) char dsm[];
    __shared__ float sb[1024];
    big_body<LEVEL>(biou, bfv, dsm, sb);
}

// =============================================================================
// Generic body (runtime level) — used ONLY by the merged small-levels kernel.
// Unchanged from R13 (committed win).
// =============================================================================
template <int STG_T, int MI>
__device__ __forceinline__ void level_body(const float* __restrict__ biou,
                                           const float* __restrict__ bfv,
                                           int level, int leaf, int nch,
                                           char* dsm, float* sb)
{
    const int MR = 64 * MI;
    const int m = 1 << level;
    const int R = BB * m;
    const __nv_bfloat16* __restrict__ h_prev = g_h[(level + 1) & 1];
    const float*         __restrict__ c_prev = g_c[(level + 1) & 1];
    float*               __restrict__ c_out  = g_c[level & 1];
    __nv_bfloat16*       __restrict__ h_out  = g_h[level & 1];

    const int tid  = threadIdx.x;
    const int lane = tid & 31;
    const int warp = tid >> 5;
    const int wm   = warp & 3;
    const int wn   = warp >> 2;
    const int M0   = blockIdx.y * MR;
    const int nt   = blockIdx.x;

    for (int i = tid; i < 768; i += 256) sb[i] = biou[i];
    for (int i = tid; i < 256; i += 256) sb[768 + i] = bfv[i];

    const uint32_t smem0 = (uint32_t)__cvta_generic_to_shared(dsm);
    const uint32_t asz = MR * 128;
    const uint32_t ssz = asz + NT * 128;

    const int lrow = tid >> 3;
    const int lch  = tid & 7;

    auto issue = [&](int K0, int buf) {
        const int kg = K0 + lch * 8;
        uint32_t abase = smem0 + buf * ssz;
        #pragma unroll
        for (int it = 0; it < 2 * MI; ++it) {
            int row = lrow + it * 32;
            int r   = M0 + row;
            const __nv_bfloat16* src = g_x;
            int sz = 0;
            if (r < R) {
                int bb   = r >> level;
                int node = r & (m - 1);
                if (kg < VV) {
                    src = g_x + ((size_t)bb * 4095 + (m - 1) + node) * VV + kg;
                    sz  = 16;
                } else if (!leaf) {
                    int j  = (kg - VV) >> 8;
                    int kh = (kg - VV) & 255;
                    src = h_prev + ((size_t)bb * (m << 1) + (node << 1) + j) * HH + kh;
                    sz  = 16;
                }
            }
            uint32_t dst = abase + row * 128 + ((lch ^ (row & 7)) << 4);
            asm volatile("cp.async.cg.shared.global [%0], [%1], 16, %2;\n"
                         :: "r"(dst), "l"(src), "r"(sz));
        }
        uint32_t bbase = abase + asz;
        #pragma unroll
        for (int it = 0; it < 5; ++it) {
            int nrow = lrow + it * 32;
            const __nv_bfloat16* src = g_Wp + (size_t)(nt * NT + nrow) * KK + kg;
            uint32_t dst = bbase + nrow * 128 + ((lch ^ (nrow & 7)) << 4);
            asm volatile("cp.async.cg.shared.global [%0], [%1], 16, 16;\n"
                         :: "r"(dst), "l"(src));
        }
        asm volatile("cp.async.commit_group;\n");
    };

    float acc[MI][10][4];
    #pragma unroll
    for (int a = 0; a < MI; ++a)
        #pragma unroll
        for (int c = 0; c < 10; ++c)
            #pragma unroll
            for (int d = 0; d < 4; ++d) acc[a][c][d] = 0.f;

    #pragma unroll
    for (int s = 0; s < STG_T; ++s) {
        if (s < nch) issue(s * KCH, s);
        else         asm volatile("cp.async.commit_group;\n");
    }

    uint32_t af[2][MI][4];
    uint32_t bq[2][4];

    for (int kc = 0; kc < nch; ++kc) {
        asm volatile("cp.async.wait_group %0;\n" :: "n"(STG_T - 1));
        __syncthreads();
        const int stg = kc % STG_T;
        const uint32_t abase = smem0 + stg * ssz;
        const uint32_t bbase = abase + asz;

        #pragma unroll
        for (int mi = 0; mi < MI; ++mi) {
            int arow = wm * (16 * MI) + mi * 16 + ((lane >> 3) & 1) * 8 + (lane & 7);
            int ach  = (lane >> 4);
            uint32_t aaddr = abase + arow * 128 + ((ach ^ (arow & 7)) << 4);
            asm volatile("ldmatrix.sync.aligned.m8n8.x4.shared.b16 {%0,%1,%2,%3}, [%4];\n"
                         : "=r"(af[0][mi][0]), "=r"(af[0][mi][1]),
                           "=r"(af[0][mi][2]), "=r"(af[0][mi][3]) : "r"(aaddr));
        }
        {
            int brow = wn * 80 + ((lane >> 4) & 1) * 8 + (lane & 7);
            int bch  = ((lane >> 3) & 1);
            uint32_t baddr = bbase + brow * 128 + ((bch ^ (brow & 7)) << 4);
            asm volatile("ldmatrix.sync.aligned.m8n8.x4.shared.b16 {%0,%1,%2,%3}, [%4];\n"
                         : "=r"(bq[0][0]), "=r"(bq[0][1]),
                           "=r"(bq[0][2]), "=r"(bq[0][3]) : "r"(baddr));
        }

        #pragma unroll
        for (int step = 0; step < 20; ++step) {
            const int p5 = step % 5;
            const int ab = (step / 5) & 1;
            if (step + 1 < 20) {
                const int nks = ((step + 1) / 5) * 16;
                const int np5 = (step + 1) % 5;
                {
                    int brow = wn * 80 + np5 * 16 + ((lane >> 4) & 1) * 8 + (lane & 7);
                    int bch  = (nks >> 3) + ((lane >> 3) & 1);
                    uint32_t baddr = bbase + brow * 128 + ((bch ^ (brow & 7)) << 4);
                    asm volatile("ldmatrix.sync.aligned.m8n8.x4.shared.b16 {%0,%1,%2,%3}, [%4];\n"
                                 : "=r"(bq[(step + 1) & 1][0]), "=r"(bq[(step + 1) & 1][1]),
                                   "=r"(bq[(step + 1) & 1][2]), "=r"(bq[(step + 1) & 1][3])
                                 : "r"(baddr));
                }
                if (np5 == 0) {
                    const int nab = ((step + 1) / 5) & 1;
                    #pragma unroll
                    for (int mi = 0; mi < MI; ++mi) {
                        int arow = wm * (16 * MI) + mi * 16 + ((lane >> 3) & 1) * 8 + (lane & 7);
                        int ach  = (nks >> 3) + (lane >> 4);
                        uint32_t aaddr = abase + arow * 128 + ((ach ^ (arow & 7)) << 4);
                        asm volatile("ldmatrix.sync.aligned.m8n8.x4.shared.b16 {%0,%1,%2,%3}, [%4];\n"
                                     : "=r"(af[nab][mi][0]), "=r"(af[nab][mi][1]),
                                       "=r"(af[nab][mi][2]), "=r"(af[nab][mi][3])
                                     : "r"(aaddr));
                    }
                }
            }
            const uint32_t* b = bq[step & 1];
            #pragma unroll
            for (int mi = 0; mi < MI; ++mi) {
                asm volatile(
                    "mma.sync.aligned.m16n8k16.row.col.f32.bf16.bf16.f32 "
                    "{%0,%1,%2,%3}, {%4,%5,%6,%7}, {%8,%9}, {%0,%1,%2,%3};\n"
                    : "+f"(acc[mi][2 * p5][0]), "+f"(acc[mi][2 * p5][1]),
                      "+f"(acc[mi][2 * p5][2]), "+f"(acc[mi][2 * p5][3])
                    : "r"(af[ab][mi][0]), "r"(af[ab][mi][1]),
                      "r"(af[ab][mi][2]), "r"(af[ab][mi][3]),
                      "r"(b[0]), "r"(b[1]));
                asm volatile(
                    "mma.sync.aligned.m16n8k16.row.col.f32.bf16.bf16.f32 "
                    "{%0,%1,%2,%3}, {%4,%5,%6,%7}, {%8,%9}, {%0,%1,%2,%3};\n"
                    : "+f"(acc[mi][2 * p5 + 1][0]), "+f"(acc[mi][2 * p5 + 1][1]),
                      "+f"(acc[mi][2 * p5 + 1][2]), "+f"(acc[mi][2 * p5 + 1][3])
                    : "r"(af[ab][mi][0]), "r"(af[ab][mi][1]),
                      "r"(af[ab][mi][2]), "r"(af[ab][mi][3]),
                      "r"(b[2]), "r"(b[3]));
            }
        }
        __syncthreads();
        if (kc + STG_T < nch) issue((kc + STG_T) * KCH, stg);
        else                  asm volatile("cp.async.commit_group;\n");
    }

    const int r0    = M0 + wm * (16 * MI) + (lane >> 2);
    const int hbase = nt * 32 + wn * 16 + ((lane & 3) << 1);
    #pragma unroll
    for (int mi = 0; mi < MI; ++mi) {
        #pragma unroll
        for (int e = 0; e < 2; ++e) {
            int r = r0 + mi * 16 + e * 8;
            if (r >= R) continue;
            float cp0[2][2], cp1[2][2];
            if (!leaf) {
                int bb = r >> level, node = r & (m - 1);
                size_t chb = ((size_t)bb * (m << 1) + (node << 1)) * HH;
                #pragma unroll
                for (int u = 0; u < 2; ++u) {
                    float2 v0 = __ldcg((const float2*)(c_prev + chb + hbase + u * 8));
                    float2 v1 = __ldcg((const float2*)(c_prev + chb + HH + hbase + u * 8));
                    cp0[u][0] = v0.x; cp0[u][1] = v0.y;
                    cp1[u][0] = v1.x; cp1[u][1] = v1.y;
                }
            } else {
                #pragma unroll
                for (int u = 0; u < 2; ++u)
                    cp0[u][0] = cp0[u][1] = cp1[u][0] = cp1[u][1] = 0.f;
            }
            #pragma unroll
            for (int u = 0; u < 2; ++u) {
                int h = hbase + u * 8;
                float cv[2], hv[2];
                #pragma unroll
                for (int q = 0; q < 2; ++q) {
                    float iv = sigf(acc[mi][0 + u][2 * e + q] + sb[h + q]);
                    float ov = sigf(acc[mi][2 + u][2 * e + q] + sb[256 + h + q]);
                    float uv = tanh_fast(acc[mi][4 + u][2 * e + q] + sb[512 + h + q]);
                    float f0 = sigf(acc[mi][6 + u][2 * e + q] + sb[768 + h + q]);
                    float f1 = sigf(acc[mi][8 + u][2 * e + q] + sb[768 + h + q]);
                    float cc = iv * uv + f0 * cp0[u][q] + f1 * cp1[u][q];
                    cv[q] = cc;
                    hv[q] = ov * tanh_fast(cc);
                }
                *(float2*)(c_out + (size_t)r * HH + h) = make_float2(cv[0], cv[1]);
                __nv_bfloat162 hp = __floats2bfloat162_rn(hv[0], hv[1]);
                *(uint32_t*)(h_out + (size_t)r * HH + h) =
                    *reinterpret_cast<uint32_t*>(&hp);
            }
        }
    }
}

// Levels 5..0 in one persistent launch (128 CTAs) + fused actor head/softmax.
__global__ __launch_bounds__(256, 1) void merged_small_kernel(
    const float* __restrict__ biou, const float* __restrict__ bfv,
    const float* __restrict__ actor_w, const float* __restrict__ actor_b,
    const float* __restrict__ vmask, float* __restrict__ out)
{
    extern __shared__ __align__(16) char dsm[];
    __shared__ float sb[1024];
    for (int l = 5; l >= 0; --l) {
        if (l == 5) level_body<5, 2>(biou, bfv, l, 0, 10, dsm, sb);
        else        level_body<5, 1>(biou, bfv, l, 0, 10, dsm, sb);
        __threadfence();
        __syncthreads();
        if (threadIdx.x == 0) {
            atomicAdd(&g_bar, 1u);
            unsigned target = (unsigned)(6 - l) * 128u;
            while (atomicAdd(&g_bar, 0u) < target) { }
        }
        __syncthreads();
    }

    if (blockIdx.y != 0) return;
    int warp = threadIdx.x >> 5;
    int lane = threadIdx.x & 31;
    int b = blockIdx.x * 8 + warp;
    const unsigned* hr = (const unsigned*)(g_h[0] + (size_t)b * HH);

    float hvv[8];
    unsigned hu[4];
    #pragma unroll
    for (int i = 0; i < 4; ++i) hu[i] = __ldcg(hr + lane + i * 32);
    #pragma unroll
    for (int i = 0; i < 4; ++i) {
        __nv_bfloat162 p = *reinterpret_cast<__nv_bfloat162*>(&hu[i]);
        hvv[i * 2]     = __bfloat162float(p.x);
        hvv[i * 2 + 1] = __bfloat162float(p.y);
    }

    float lg[NOPS];
    #pragma unroll
    for (int o = 0; o < NOPS; ++o) {
        float s = 0.f;
        #pragma unroll
        for (int i = 0; i < 4; ++i) {
            int hh = (lane + i * 32) * 2;
            s += hvv[i * 2]     * actor_w[o * HH + hh];
            s += hvv[i * 2 + 1] * actor_w[o * HH + hh + 1];
        }
        #pragma unroll
        for (int off = 16; off; off >>= 1) s += __shfl_xor_sync(0xffffffffu, s, off);
        float mk = vmask[b * NOPS + o];
        lg[o] = logf(mk) + s * mk + actor_b[o] * mk;
    }
    if (lane == 0) {
        float mx = -1e30f;
        #pragma unroll
        for (int o = 0; o < NOPS; ++o) {
            lg[o] = lg[o] / 3.0f;           // TEMP
            if (lg[o] > mx) mx = lg[o];
        }
        float ev[NOPS], sum = 0.f;
        #pragma unroll
        for (int o = 0; o < NOPS; ++o) { ev[o] = expf(lg[o] - mx); sum += ev[o]; }
        float inv = 1.0f / sum;
        #pragma unroll
        for (int o = 0; o < NOPS; ++o) out[b * NOPS + o] = ev[o] * inv;
    }
}

// ---------------- launch ------------------------------------------------------
extern "C" void kernel_launch(void* const* d_in, const int* in_sizes, int n_in,
                              void* d_out, int out_size)
{
    const float* arg_hot = (const float*)d_in[0];
    const float* Wiou    = (const float*)d_in[1];
    const float* biou    = (const float*)d_in[2];
    const float* Uiou    = (const float*)d_in[3];
    const float* Wf      = (const float*)d_in[4];
    const float* bfv     = (const float*)d_in[5];
    const float* Uf      = (const float*)d_in[6];
    const float* actor_w = (const float*)d_in[7];
    const float* actor_b = (const float*)d_in[8];
    const float* vmask   = (const float*)d_in[9];
    float* out = (float*)d_out;

    cudaFuncSetAttribute(fused_big<11>, cudaFuncAttributeMaxDynamicSharedMemorySize, SMEM_BIG);
    cudaFuncSetAttribute(fused_big<10>, cudaFuncAttributeMaxDynamicSharedMemorySize, SMEM_BIG);
    cudaFuncSetAttribute(fused_big<9>,  cudaFuncAttributeMaxDynamicSharedMemorySize, SMEM_BIG);
    cudaFuncSetAttribute(fused_big<8>,  cudaFuncAttributeMaxDynamicSharedMemorySize, SMEM_BIG);
    cudaFuncSetAttribute(fused_big<7>,  cudaFuncAttributeMaxDynamicSharedMemorySize, SMEM_BIG);
    cudaFuncSetAttribute(fused_big<6>,  cudaFuncAttributeMaxDynamicSharedMemorySize, SMEM_BIG);
    cudaFuncSetAttribute(merged_small_kernel,
                         cudaFuncAttributeMaxDynamicSharedMemorySize, SMEM_SMALL);

    prep_all_kernel<<<35960, 256>>>(arg_hot, Wiou, Uiou, Wf, Uf);

    fused_big<11><<<dim3(8, 1024), 256, SMEM_BIG>>>(biou, bfv);
    fused_big<10><<<dim3(8,  512), 256, SMEM_BIG>>>(biou, bfv);
    fused_big<9><<<dim3(8,   256), 256, SMEM_BIG>>>(biou, bfv);
    fused_big<8><<<dim3(8,   128), 256, SMEM_BIG>>>(biou, bfv);
    fused_big<7><<<dim3(8,    64), 256, SMEM_BIG>>>(biou, bfv);
    fused_big<6><<<dim3(8,    32), 256, SMEM_BIG>>>(biou, bfv);

    merged_small_kernel<<<dim3(8, 16), 256, SMEM_SMALL>>>(
        biou, bfv, actor_w, actor_b, vmask, out);
}